// round 3
// baseline (speedup 1.0000x reference)
#include <cuda_runtime.h>
#include <math.h>

#define A_MAX    442368
#define NKEEP    1000
#define CAND_CAP 2048
#define HIST_N   1024

// ---------------- scratch (device globals; no allocation allowed) ----------------
__device__ unsigned            g_key[A_MAX];      // bits of m = 1 - score (ascending = best first)
__device__ int                 g_argmax[A_MAX];
__device__ unsigned            g_hist4k[HIST_N];  // histogram over u>>20 (exp + 3 mantissa bits)
__device__ unsigned            g_cnt;
__device__ unsigned long long  g_cand[CAND_CAP];  // ((u64)u<<32)|idx, ascending sort = top-k order
__device__ float4              g_box[NKEEP];
__device__ float               g_area[NKEEP];
__device__ float               g_cscore[NKEEP];
__device__ int                 g_ccls[NKEEP];
__device__ unsigned            g_validw[32];
__device__ unsigned            g_sup[NKEEP * 32]; // 1000 rows x 1024-bit suppression mask

// ---------------- init ----------------
__global__ void k_init() {
    int t = threadIdx.x;
    if (t < HIST_N) g_hist4k[t] = 0;
    if (t == 0)     g_cnt = 0;
}

// ---------------- stage 1: warp-per-anchor max/argmax + fused 1024-bin hist ----------------
__global__ void __launch_bounds__(256) k_reduce(const float* __restrict__ cla, int A) {
    __shared__ unsigned hist[HIST_N];
    for (int b = threadIdx.x; b < HIST_N; b += 256) hist[b] = 0;
    __syncthreads();

    int lane = threadIdx.x & 31;
    int gw   = blockIdx.x * 8 + (threadIdx.x >> 5);
    int nw   = gridDim.x * 8;

    for (int a = gw; a < A; a += 2 * nw) {
        int a2 = a + nw;
        bool h2 = a2 < A;
        const float* p  = cla + (size_t)a * 80;
        const float* p2 = cla + (size_t)(h2 ? a2 : a) * 80;

        float f0a = p[lane],  f1a = p[32 + lane];
        float f2a = (lane < 16) ? p[64 + lane] : -3.0e38f;
        float f0b = p2[lane], f1b = p2[32 + lane];
        float f2b = (lane < 16) ? p2[64 + lane] : -3.0e38f;

        float va = f0a; int ixa = lane;
        if (f1a > va) { va = f1a; ixa = lane + 32; }
        if (f2a > va) { va = f2a; ixa = lane + 64; }
        float vb = f0b; int ixb = lane;
        if (f1b > vb) { vb = f1b; ixb = lane + 32; }
        if (f2b > vb) { vb = f2b; ixb = lane + 64; }

#pragma unroll
        for (int off = 16; off; off >>= 1) {
            float ova = __shfl_down_sync(0xFFFFFFFFu, va, off);
            int   oia = __shfl_down_sync(0xFFFFFFFFu, ixa, off);
            float ovb = __shfl_down_sync(0xFFFFFFFFu, vb, off);
            int   oib = __shfl_down_sync(0xFFFFFFFFu, ixb, off);
            if (ova > va || (ova == va && oia < ixa)) { va = ova; ixa = oia; }
            if (ovb > vb || (ovb == vb && oib < ixb)) { vb = ovb; ixb = oib; }
        }

        if (lane == 0) {
            float ma = fmaxf(1.0f - va, 0.0f);
            unsigned ua = __float_as_uint(ma);
            g_key[a] = ua; g_argmax[a] = ixa;
            atomicAdd(&hist[min(ua >> 20, (unsigned)(HIST_N - 1))], 1u);
            if (h2) {
                float mb = fmaxf(1.0f - vb, 0.0f);
                unsigned ub = __float_as_uint(mb);
                g_key[a2] = ub; g_argmax[a2] = ixb;
                atomicAdd(&hist[min(ub >> 20, (unsigned)(HIST_N - 1))], 1u);
            }
        }
    }
    __syncthreads();
    for (int b = threadIdx.x; b < HIST_N; b += 256) {
        unsigned s = hist[b];
        if (s) atomicAdd(&g_hist4k[b], s);
    }
}

// ---------------- stage 2: pick threshold bin, compact candidates ----------------
__global__ void __launch_bounds__(256) k_compact(int A4) {
    __shared__ unsigned scn[256];
    __shared__ unsigned sB;
    int t = threadIdx.x;

    uint4 h = ((const uint4*)g_hist4k)[t];     // bins 4t..4t+3
    unsigned ls = h.x + h.y + h.z + h.w;
    scn[t] = ls;
    __syncthreads();
    for (int off = 1; off < 256; off <<= 1) {
        unsigned v = (t >= off) ? scn[t - off] : 0u;
        __syncthreads();
        scn[t] += v;
        __syncthreads();
    }
    unsigned cum  = scn[t];
    unsigned prev = cum - ls;
    if (prev < NKEEP && cum >= NKEEP) {
        unsigned r = prev, B = 4 * t;
        if      (r + h.x >= NKEEP) B = 4 * t;
        else if (r + h.x + h.y >= NKEEP) B = 4 * t + 1;
        else if (r + h.x + h.y + h.z >= NKEEP) B = 4 * t + 2;
        else B = 4 * t + 3;
        sB = B;
    }
    __syncthreads();
    unsigned B = sB;

    for (int i = blockIdx.x * 256 + t; i < A4; i += gridDim.x * 256) {
        uint4 k4 = ((const uint4*)g_key)[i];
        unsigned base = 4u * (unsigned)i;
        if ((k4.x >> 20) <= B) { unsigned s = atomicAdd(&g_cnt, 1u); if (s < CAND_CAP) g_cand[s] = (((unsigned long long)k4.x) << 32) | base; }
        if ((k4.y >> 20) <= B) { unsigned s = atomicAdd(&g_cnt, 1u); if (s < CAND_CAP) g_cand[s] = (((unsigned long long)k4.y) << 32) | (base + 1); }
        if ((k4.z >> 20) <= B) { unsigned s = atomicAdd(&g_cnt, 1u); if (s < CAND_CAP) g_cand[s] = (((unsigned long long)k4.z) << 32) | (base + 2); }
        if ((k4.w >> 20) <= B) { unsigned s = atomicAdd(&g_cnt, 1u); if (s < CAND_CAP) g_cand[s] = (((unsigned long long)k4.w) << 32) | (base + 3); }
    }
}

// ---------------- stage 3: sort candidates, decode + clip top-1000 ----------------
__global__ void __launch_bounds__(1024) k_sortgather(const float4* __restrict__ anchors,
                                                     const float4* __restrict__ reg) {
    __shared__ unsigned long long s[CAND_CAP];
    unsigned n = g_cnt; if (n > CAND_CAP) n = CAND_CAP;
    for (int i = threadIdx.x; i < CAND_CAP; i += 1024)
        s[i] = (i < (int)n) ? g_cand[i] : 0xFFFFFFFFFFFFFFFFull;
    __syncthreads();

    for (unsigned kk = 2; kk <= CAND_CAP; kk <<= 1) {
        for (unsigned j = kk >> 1; j > 0; j >>= 1) {
            for (unsigned base = 0; base < CAND_CAP; base += 1024) {
                unsigned i = base + threadIdx.x;
                unsigned ixj = i ^ j;
                if (ixj > i) {
                    unsigned long long av = s[i], bv = s[ixj];
                    bool up = ((i & kk) == 0);
                    if ((av > bv) == up) { s[i] = bv; s[ixj] = av; }
                }
            }
            __syncthreads();
        }
    }

    int i = threadIdx.x;
    bool kpv = false;
    if (i < NKEEP) {
        unsigned long long kk = s[i];
        unsigned idx = (unsigned)kk;
        float m  = __uint_as_float((unsigned)(kk >> 32));
        float sc = 1.0f - m;

        float4 an = anchors[idx];
        float4 dg = reg[idx];
        float wa = an.z - an.x, ha = an.w - an.y;
        float cxa = an.x + 0.5f * wa, cya = an.y + 0.5f * ha;
        float cx = cxa + dg.x * wa, cy = cya + dg.y * ha;
        float w  = wa * expf(dg.z), hh = ha * expf(dg.w);
        float x1 = fminf(fmaxf(cx - 0.5f * w, 0.0f), 1535.0f);
        float y1 = fminf(fmaxf(cy - 0.5f * hh, 0.0f), 1535.0f);
        float x2 = fminf(fmaxf(cx + 0.5f * w, 0.0f), 1535.0f);
        float y2 = fminf(fmaxf(cy + 0.5f * hh, 0.0f), 1535.0f);

        g_box[i]    = make_float4(x1, y1, x2, y2);
        g_area[i]   = fmaxf(x2 - x1, 0.0f) * fmaxf(y2 - y1, 0.0f);
        g_cscore[i] = sc;
        g_ccls[i]   = g_argmax[idx];
        kpv = (sc > 0.5f);
    }
    unsigned bm = __ballot_sync(0xFFFFFFFFu, kpv);
    if ((threadIdx.x & 31) == 0) g_validw[threadIdx.x >> 5] = bm;
}

// ---------------- stage 4: suppression mask (smem-staged boxes) ----------------
__global__ void __launch_bounds__(256) k_iou() {
    __shared__ float4 sbox[NKEEP];
    __shared__ float  sarea[NKEEP];
    int t = threadIdx.x;
    for (int i = t; i < NKEEP; i += 256) { sbox[i] = g_box[i]; sarea[i] = g_area[i]; }
    __syncthreads();

    int W    = blockIdx.x * 8 + (t >> 5);   // 0..1023
    int lane = t & 31;
    int jw    = W & 31;
    int chunk = W >> 5;
    int i0   = chunk * 32;
    int iend = i0 + 32; if (iend > NKEEP) iend = NKEEP;
    int j = jw * 32 + lane;
    bool jv = (j < NKEEP);
    float jx1 = 0, jy1 = 0, jx2 = 0, jy2 = 0, ja = 0;
    if (jv) {
        float4 b = sbox[j];
        jx1 = b.x; jy1 = b.y; jx2 = b.z; jy2 = b.w;
        ja = sarea[j];
    }
    for (int i = i0; i < iend; i++) {
        float4 bi = sbox[i];
        float ai  = sarea[i];
        float iw = fminf(bi.z, jx2) - fmaxf(bi.x, jx1); iw = fmaxf(iw, 0.0f);
        float ih = fminf(bi.w, jy2) - fmaxf(bi.y, jy1); ih = fmaxf(ih, 0.0f);
        float inter = iw * ih;
        float uni   = ai + ja - inter;
        bool pred = jv && (inter / fmaxf(uni, 1e-8f) > 0.5f);
        unsigned m = __ballot_sync(0xFFFFFFFFu, pred);
        if (lane == 0) g_sup[i * 32 + jw] = m;
    }
}

// ---------------- stage 5: sequential NMS scan with skip + output ----------------
__global__ void k_scan(float* __restrict__ out) {
    extern __shared__ unsigned ssup[];   // 32000 words = 125 KB
    __shared__ unsigned skeep[32];
    int tid = threadIdx.x;
    for (int w = tid; w < NKEEP * 32; w += blockDim.x) ssup[w] = g_sup[w];
    __syncthreads();

    if (tid < 32) {
        int lane = tid;
        unsigned removed = 0;            // my j-word of the removed set
        unsigned keep = 0;               // bits for i in [lane*32, lane*32+32)
        unsigned validw = g_validw[lane];
        for (int blk = 0; blk < 32; blk++) {
            unsigned W = __shfl_sync(0xFFFFFFFFu, removed, blk);  // replica of block word
            unsigned V = __shfl_sync(0xFFFFFFFFu, validw,  blk);
            int i0 = blk * 32;
            int nb = NKEEP - i0; if (nb > 32) nb = 32;
            for (int b = 0; b < nb; b++) {
                bool kept = !((W >> b) & 1u) && ((V >> b) & 1u);   // uniform across lanes
                if (kept) {
                    unsigned row = ssup[(i0 + b) * 32 + lane];
                    removed |= row;
                    W |= __shfl_sync(0xFFFFFFFFu, row, blk);
                    if (lane == blk) keep |= 1u << b;
                }
            }
        }
        skeep[lane] = keep;
    }
    __syncthreads();

    if (tid < NKEEP) {
        bool kp = (skeep[tid >> 5] >> (tid & 31)) & 1u;
        out[tid]         = kp ? g_cscore[tid] : 0.0f;
        out[NKEEP + tid] = kp ? (float)g_ccls[tid] : -1.0f;
        float4 b = kp ? g_box[tid] : make_float4(0, 0, 0, 0);
        ((float4*)(out + 2 * NKEEP))[tid] = b;
    }
}

// ---------------- launch ----------------
extern "C" void kernel_launch(void* const* d_in, const int* in_sizes, int n_in,
                              void* d_out, int out_size) {
    const float*  cla     = (const float*)d_in[0];
    const float4* reg     = (const float4*)d_in[1];
    const float4* anchors = (const float4*)d_in[2];
    int A = in_sizes[0] / 80;
    float* out = (float*)d_out;

    cudaFuncSetAttribute(k_scan, cudaFuncAttributeMaxDynamicSharedMemorySize, 131072);

    k_init<<<1, 1024>>>();
    k_reduce<<<1184, 256>>>(cla, A);
    k_compact<<<592, 256>>>(A / 4);
    k_sortgather<<<1, 1024>>>(anchors, reg);
    k_iou<<<128, 256>>>();
    k_scan<<<1, 1024, NKEEP * 32 * sizeof(unsigned)>>>(out);
}

// round 4
// speedup vs baseline: 1.2533x; 1.2533x over previous
#include <cuda_runtime.h>
#include <math.h>

#define A_MAX    442368
#define NKEEP    1000
#define CAND_CAP 2048
#define HIST_N   1024

// ---------------- scratch (device globals; no allocation allowed) ----------------
__device__ unsigned            g_key[A_MAX];      // bits of m = 1 - score (ascending = best first)
__device__ int                 g_argmax[A_MAX];
__device__ unsigned            g_hist4k[HIST_N];  // histogram over u>>20
__device__ unsigned            g_cnt;
__device__ unsigned long long  g_cand[CAND_CAP];  // ((u64)u<<32)|idx
__device__ float4              g_box[NKEEP];
__device__ float               g_area[NKEEP];
__device__ float               g_cscore[NKEEP];
__device__ int                 g_ccls[NKEEP];
__device__ unsigned            g_sup[NKEEP * 32]; // 1000 rows x 1024-bit suppression mask

// ---------------- init ----------------
__global__ void k_init() {
    int t = threadIdx.x;
    if (t < HIST_N) g_hist4k[t] = 0;
    if (t == 0)     g_cnt = 0;
}

// ---------------- stage 1: warp-per-anchor max/argmax + fused 1024-bin hist ----------------
__global__ void __launch_bounds__(256) k_reduce(const float* __restrict__ cla, int A) {
    __shared__ unsigned hist[HIST_N];
    for (int b = threadIdx.x; b < HIST_N; b += 256) hist[b] = 0;
    __syncthreads();

    int lane = threadIdx.x & 31;
    int gw   = blockIdx.x * 8 + (threadIdx.x >> 5);
    int nw   = gridDim.x * 8;

    for (int a = gw; a < A; a += 2 * nw) {
        int a2 = a + nw;
        bool h2 = a2 < A;
        const float* p  = cla + (size_t)a * 80;
        const float* p2 = cla + (size_t)(h2 ? a2 : a) * 80;

        float f0a = p[lane],  f1a = p[32 + lane];
        float f2a = (lane < 16) ? p[64 + lane] : -3.0e38f;
        float f0b = p2[lane], f1b = p2[32 + lane];
        float f2b = (lane < 16) ? p2[64 + lane] : -3.0e38f;

        float va = f0a; int ixa = lane;
        if (f1a > va) { va = f1a; ixa = lane + 32; }
        if (f2a > va) { va = f2a; ixa = lane + 64; }
        float vb = f0b; int ixb = lane;
        if (f1b > vb) { vb = f1b; ixb = lane + 32; }
        if (f2b > vb) { vb = f2b; ixb = lane + 64; }

#pragma unroll
        for (int off = 16; off; off >>= 1) {
            float ova = __shfl_down_sync(0xFFFFFFFFu, va, off);
            int   oia = __shfl_down_sync(0xFFFFFFFFu, ixa, off);
            float ovb = __shfl_down_sync(0xFFFFFFFFu, vb, off);
            int   oib = __shfl_down_sync(0xFFFFFFFFu, ixb, off);
            if (ova > va || (ova == va && oia < ixa)) { va = ova; ixa = oia; }
            if (ovb > vb || (ovb == vb && oib < ixb)) { vb = ovb; ixb = oib; }
        }

        if (lane == 0) {
            float ma = fmaxf(1.0f - va, 0.0f);
            unsigned ua = __float_as_uint(ma);
            g_key[a] = ua; g_argmax[a] = ixa;
            atomicAdd(&hist[min(ua >> 20, (unsigned)(HIST_N - 1))], 1u);
            if (h2) {
                float mb = fmaxf(1.0f - vb, 0.0f);
                unsigned ub = __float_as_uint(mb);
                g_key[a2] = ub; g_argmax[a2] = ixb;
                atomicAdd(&hist[min(ub >> 20, (unsigned)(HIST_N - 1))], 1u);
            }
        }
    }
    __syncthreads();
    for (int b = threadIdx.x; b < HIST_N; b += 256) {
        unsigned s = hist[b];
        if (s) atomicAdd(&g_hist4k[b], s);
    }
}

// ---------------- stage 2: pick threshold bin, compact candidates ----------------
__global__ void __launch_bounds__(256) k_compact(int A4) {
    __shared__ unsigned scn[256];
    __shared__ unsigned sB;
    int t = threadIdx.x;

    uint4 h = ((const uint4*)g_hist4k)[t];     // bins 4t..4t+3
    unsigned ls = h.x + h.y + h.z + h.w;
    scn[t] = ls;
    __syncthreads();
    for (int off = 1; off < 256; off <<= 1) {
        unsigned v = (t >= off) ? scn[t - off] : 0u;
        __syncthreads();
        scn[t] += v;
        __syncthreads();
    }
    unsigned cum  = scn[t];
    unsigned prev = cum - ls;
    if (prev < NKEEP && cum >= NKEEP) {
        unsigned r = prev, B;
        if      (r + h.x >= NKEEP) B = 4 * t;
        else if (r + h.x + h.y >= NKEEP) B = 4 * t + 1;
        else if (r + h.x + h.y + h.z >= NKEEP) B = 4 * t + 2;
        else B = 4 * t + 3;
        sB = B;
    }
    __syncthreads();
    unsigned B = sB;

    for (int i = blockIdx.x * 256 + t; i < A4; i += gridDim.x * 256) {
        uint4 k4 = ((const uint4*)g_key)[i];
        unsigned base = 4u * (unsigned)i;
        if ((k4.x >> 20) <= B) { unsigned s = atomicAdd(&g_cnt, 1u); if (s < CAND_CAP) g_cand[s] = (((unsigned long long)k4.x) << 32) | base; }
        if ((k4.y >> 20) <= B) { unsigned s = atomicAdd(&g_cnt, 1u); if (s < CAND_CAP) g_cand[s] = (((unsigned long long)k4.y) << 32) | (base + 1); }
        if ((k4.z >> 20) <= B) { unsigned s = atomicAdd(&g_cnt, 1u); if (s < CAND_CAP) g_cand[s] = (((unsigned long long)k4.z) << 32) | (base + 2); }
        if ((k4.w >> 20) <= B) { unsigned s = atomicAdd(&g_cnt, 1u); if (s < CAND_CAP) g_cand[s] = (((unsigned long long)k4.w) << 32) | (base + 3); }
    }
}

// ---------------- stage 3: parallel rank-by-counting + decode/clip scatter ----------------
// 32 blocks x 256 threads; 4 threads cooperate per candidate slot (8192 threads / 2048 slots)
__global__ void __launch_bounds__(256) k_rank(const float4* __restrict__ anchors,
                                              const float4* __restrict__ reg) {
    __shared__ unsigned long long s[CAND_CAP];
    __shared__ unsigned sn;
    int t = threadIdx.x;
    if (t == 0) { unsigned c = g_cnt; sn = (c > CAND_CAP) ? CAND_CAP : c; }
    __syncthreads();
    unsigned n = sn;
    for (int i = t; i < CAND_CAP; i += 256)
        s[i] = (i < (int)n) ? g_cand[i] : 0xFFFFFFFFFFFFFFFFull;
    __syncthreads();

    unsigned gt   = blockIdx.x * 256 + t;   // 0..8191
    unsigned slot = gt >> 2;                // 0..2047
    unsigned q    = gt & 3;                 // quarter
    if (slot >= n) return;

    unsigned long long mine = s[slot];
    unsigned j0 = q * (CAND_CAP / 4), j1 = j0 + (CAND_CAP / 4);
    if (j1 > n) j1 = n;
    unsigned r = 0;
    for (unsigned j = j0; j < j1; j++) r += (s[j] < mine);
    r += __shfl_xor_sync(0xFFFFFFFFu, r, 1);
    r += __shfl_xor_sync(0xFFFFFFFFu, r, 2);

    if (q == 0 && r < NKEEP) {
        unsigned idx = (unsigned)mine;
        float m  = __uint_as_float((unsigned)(mine >> 32));
        float sc = 1.0f - m;

        float4 an = anchors[idx];
        float4 dg = reg[idx];
        float wa = an.z - an.x, ha = an.w - an.y;
        float cxa = an.x + 0.5f * wa, cya = an.y + 0.5f * ha;
        float cx = cxa + dg.x * wa, cy = cya + dg.y * ha;
        float w  = wa * expf(dg.z), hh = ha * expf(dg.w);
        float x1 = fminf(fmaxf(cx - 0.5f * w, 0.0f), 1535.0f);
        float y1 = fminf(fmaxf(cy - 0.5f * hh, 0.0f), 1535.0f);
        float x2 = fminf(fmaxf(cx + 0.5f * w, 0.0f), 1535.0f);
        float y2 = fminf(fmaxf(cy + 0.5f * hh, 0.0f), 1535.0f);

        g_box[r]    = make_float4(x1, y1, x2, y2);
        g_area[r]   = fmaxf(x2 - x1, 0.0f) * fmaxf(y2 - y1, 0.0f);
        g_cscore[r] = sc;
        g_ccls[r]   = g_argmax[idx];
    }
}

// ---------------- stage 4: suppression mask (smem-staged boxes) ----------------
__global__ void __launch_bounds__(256) k_iou() {
    __shared__ float4 sbox[NKEEP];
    __shared__ float  sarea[NKEEP];
    int t = threadIdx.x;
    for (int i = t; i < NKEEP; i += 256) { sbox[i] = g_box[i]; sarea[i] = g_area[i]; }
    __syncthreads();

    int W    = blockIdx.x * 8 + (t >> 5);   // 0..1023
    int lane = t & 31;
    int jw    = W & 31;
    int chunk = W >> 5;
    int i0   = chunk * 32;
    int iend = i0 + 32; if (iend > NKEEP) iend = NKEEP;
    int j = jw * 32 + lane;
    bool jv = (j < NKEEP);
    float jx1 = 0, jy1 = 0, jx2 = 0, jy2 = 0, ja = 0;
    if (jv) {
        float4 b = sbox[j];
        jx1 = b.x; jy1 = b.y; jx2 = b.z; jy2 = b.w;
        ja = sarea[j];
    }
    for (int i = i0; i < iend; i++) {
        float4 bi = sbox[i];
        float ai  = sarea[i];
        float iw = fminf(bi.z, jx2) - fmaxf(bi.x, jx1); iw = fmaxf(iw, 0.0f);
        float ih = fminf(bi.w, jy2) - fmaxf(bi.y, jy1); ih = fmaxf(ih, 0.0f);
        float inter = iw * ih;
        float uni   = ai + ja - inter;
        bool pred = jv && (inter / fmaxf(uni, 1e-8f) > 0.5f);
        unsigned m = __ballot_sync(0xFFFFFFFFu, pred);
        if (lane == 0) g_sup[i * 32 + jw] = m;
    }
}

// ---------------- stage 5: tile-blocked sequential NMS + output (128 threads) ----------------
__global__ void __launch_bounds__(128) k_scan(float* __restrict__ out) {
    extern __shared__ unsigned ssup[];   // 32768 words = 128 KB (tail zeroed)
    __shared__ unsigned svalid[32];
    __shared__ unsigned skeep[32];
    int tid = threadIdx.x;

    // stage sup matrix (+ zero tail rows 1000..1023)
    {
        uint4* d4 = (uint4*)ssup;
        const uint4* s4 = (const uint4*)g_sup;
        for (int i = tid; i < 8192; i += 128)
            d4[i] = (i < 8000) ? s4[i] : make_uint4(0, 0, 0, 0);
    }
    // valid bits from scores (tiles 0..31, indices tid.. with stride 128 cover 1024? no)
    for (int base = 0; base < 1024; base += 128) {
        int i = base + tid;
        float sc = (i < NKEEP) ? g_cscore[i] : 0.0f;
        unsigned bm = __ballot_sync(0xFFFFFFFFu, sc > 0.5f);
        if ((tid & 31) == 0) svalid[i >> 5] = bm;
    }
    __syncthreads();

    if (tid < 32) {
        int lane = tid;
        unsigned rem = 0;       // bit s = index 32*s + lane suppressed by earlier kept
        unsigned keepw = 0;     // keep word for tile == lane
        unsigned validw = svalid[lane];
        for (int t = 0; t < 32; t++) {
            unsigned rowv[32];
#pragma unroll
            for (int b = 0; b < 32; b++)
                rowv[b] = ssup[(32 * t + b) * 32 + t];      // broadcast LDS
            unsigned W = __ballot_sync(0xFFFFFFFFu, (rem >> t) & 1u);
            unsigned V = __shfl_sync(0xFFFFFFFFu, validw, t);
            unsigned K = 0;
#pragma unroll
            for (int b = 0; b < 32; b++) {
                if (((V >> b) & 1u) && !((W >> b) & 1u) && ((rowv[b] & K) == 0u))
                    K |= 1u << b;
            }
            if (lane == t) keepw = K;
            // propagate: index 32*s+lane suppressed if its tile-t row word hits K
#pragma unroll
            for (int s = 1; s < 32; s++) {
                if (s > t) {
                    unsigned c = ssup[(32 * s + lane) * 32 + t];
                    if (c & K) rem |= 1u << s;
                }
            }
        }
        skeep[lane] = keepw;
    }
    __syncthreads();

    for (int base = 0; base < NKEEP; base += 128) {
        int i = base + tid;
        if (i < NKEEP) {
            bool kp = (skeep[i >> 5] >> (i & 31)) & 1u;
            out[i]         = kp ? g_cscore[i] : 0.0f;
            out[NKEEP + i] = kp ? (float)g_ccls[i] : -1.0f;
            float4 b = kp ? g_box[i] : make_float4(0, 0, 0, 0);
            ((float4*)(out + 2 * NKEEP))[i] = b;
        }
    }
}

// ---------------- launch ----------------
extern "C" void kernel_launch(void* const* d_in, const int* in_sizes, int n_in,
                              void* d_out, int out_size) {
    const float*  cla     = (const float*)d_in[0];
    const float4* reg     = (const float4*)d_in[1];
    const float4* anchors = (const float4*)d_in[2];
    int A = in_sizes[0] / 80;
    float* out = (float*)d_out;

    cudaFuncSetAttribute(k_scan, cudaFuncAttributeMaxDynamicSharedMemorySize, 131072);

    k_init<<<1, 1024>>>();
    k_reduce<<<1184, 256>>>(cla, A);
    k_compact<<<592, 256>>>(A / 4);
    k_rank<<<32, 256>>>(anchors, reg);
    k_iou<<<128, 256>>>();
    k_scan<<<1, 128, 131072>>>(out);
}

// round 9
// speedup vs baseline: 1.6570x; 1.3221x over previous
#include <cuda_runtime.h>
#include <math.h>

#define A_MAX    442368
#define NKEEP    1000
#define CAND_CAP 2048
#define HIST_N   1024
#define SCAN_STRIDE 33   // 32 data words + 1 pad -> conflict-free propagate loads

// ---------------- scratch (device globals; no allocation allowed) ----------------
__device__ unsigned            g_key[A_MAX];      // bits of m = 1 - score (ascending = best first)
__device__ int                 g_argmax[A_MAX];
__device__ unsigned            g_hist4k[HIST_N];  // histogram over u>>20
__device__ unsigned            g_cnt;
__device__ unsigned long long  g_cand[CAND_CAP];  // ((u64)u<<32)|idx
__device__ float4              g_box[NKEEP];
__device__ float               g_area[NKEEP];
__device__ float               g_cscore[NKEEP];
__device__ int                 g_ccls[NKEEP];
__device__ unsigned            g_sup[NKEEP * 32]; // 1000 rows x 1024-bit suppression mask

// Integer redux (sm_80+; f32 redux is NOT supported on sm_103).
__device__ __forceinline__ unsigned warp_max_u32(unsigned v) {
    unsigned r;
    asm("redux.sync.max.u32 %0, %1, 0xffffffff;" : "=r"(r) : "r"(v));
    return r;
}
__device__ __forceinline__ unsigned warp_min_u32(unsigned v) {
    unsigned r;
    asm("redux.sync.min.u32 %0, %1, 0xffffffff;" : "=r"(r) : "r"(v));
    return r;
}

// ---------------- init ----------------
__global__ void k_init() {
    int t = threadIdx.x;
    if (t < HIST_N) g_hist4k[t] = 0;
    if (t == 0)     g_cnt = 0;
}

// ---------------- stage 1: warp-per-anchor max/argmax (integer redux on bits) ----------------
__global__ void __launch_bounds__(256) k_reduce(const float* __restrict__ cla, int A) {
    __shared__ unsigned hist[HIST_N];
    for (int b = threadIdx.x; b < HIST_N; b += 256) hist[b] = 0;
    __syncthreads();

    int lane = threadIdx.x & 31;
    int gw   = blockIdx.x * 8 + (threadIdx.x >> 5);
    int nw   = gridDim.x * 8;

    for (int a = gw; a < A; a += 2 * nw) {
        int a2 = a + nw;
        bool h2 = a2 < A;
        const float* p  = cla + (size_t)a * 80;
        const float* p2 = cla + (size_t)(h2 ? a2 : a) * 80;

        // scores are uniform[0,1) -> non-negative -> bit pattern is monotone
        float f0a = p[lane],  f1a = p[32 + lane];
        float f2a = (lane < 16) ? p[64 + lane] : 0.0f;   // 0.0 can't win (real scores > 0)
        float f0b = p2[lane], f1b = p2[32 + lane];
        float f2b = (lane < 16) ? p2[64 + lane] : 0.0f;

        float va = f0a; int ixa = lane;
        if (f1a > va) { va = f1a; ixa = lane + 32; }
        if (f2a > va) { va = f2a; ixa = lane + 64; }
        float vb = f0b; int ixb = lane;
        if (f1b > vb) { vb = f1b; ixb = lane + 32; }
        if (f2b > vb) { vb = f2b; ixb = lane + 64; }

        unsigned mba = warp_max_u32(__float_as_uint(va));
        unsigned mbb = warp_max_u32(__float_as_uint(vb));
        float mva = __uint_as_float(mba);
        float mvb = __uint_as_float(mbb);
        unsigned cia = (__float_as_uint(va) == mba) ? (unsigned)ixa : 0xFFFFu;
        unsigned cib = (__float_as_uint(vb) == mbb) ? (unsigned)ixb : 0xFFFFu;
        unsigned mia = warp_min_u32(cia);
        unsigned mib = warp_min_u32(cib);

        if (lane == 0) {
            float ma = fmaxf(1.0f - mva, 0.0f);
            unsigned ua = __float_as_uint(ma);
            g_key[a] = ua; g_argmax[a] = (int)mia;
            atomicAdd(&hist[min(ua >> 20, (unsigned)(HIST_N - 1))], 1u);
            if (h2) {
                float mb = fmaxf(1.0f - mvb, 0.0f);
                unsigned ub = __float_as_uint(mb);
                g_key[a2] = ub; g_argmax[a2] = (int)mib;
                atomicAdd(&hist[min(ub >> 20, (unsigned)(HIST_N - 1))], 1u);
            }
        }
    }
    __syncthreads();
    for (int b = threadIdx.x; b < HIST_N; b += 256) {
        unsigned s = hist[b];
        if (s) atomicAdd(&g_hist4k[b], s);
    }
}

// ---------------- stage 2: pick threshold bin, compact candidates ----------------
__global__ void __launch_bounds__(256) k_compact(int A4) {
    __shared__ unsigned scn[256];
    __shared__ unsigned sB;
    int t = threadIdx.x;

    uint4 h = ((const uint4*)g_hist4k)[t];     // bins 4t..4t+3
    unsigned ls = h.x + h.y + h.z + h.w;
    scn[t] = ls;
    __syncthreads();
    for (int off = 1; off < 256; off <<= 1) {
        unsigned v = (t >= off) ? scn[t - off] : 0u;
        __syncthreads();
        scn[t] += v;
        __syncthreads();
    }
    unsigned cum  = scn[t];
    unsigned prev = cum - ls;
    if (prev < NKEEP && cum >= NKEEP) {
        unsigned r = prev, B;
        if      (r + h.x >= NKEEP) B = 4 * t;
        else if (r + h.x + h.y >= NKEEP) B = 4 * t + 1;
        else if (r + h.x + h.y + h.z >= NKEEP) B = 4 * t + 2;
        else B = 4 * t + 3;
        sB = B;
    }
    __syncthreads();
    unsigned B = sB;

    for (int i = blockIdx.x * 256 + t; i < A4; i += gridDim.x * 256) {
        uint4 k4 = ((const uint4*)g_key)[i];
        unsigned base = 4u * (unsigned)i;
        if ((k4.x >> 20) <= B) { unsigned s = atomicAdd(&g_cnt, 1u); if (s < CAND_CAP) g_cand[s] = (((unsigned long long)k4.x) << 32) | base; }
        if ((k4.y >> 20) <= B) { unsigned s = atomicAdd(&g_cnt, 1u); if (s < CAND_CAP) g_cand[s] = (((unsigned long long)k4.y) << 32) | (base + 1); }
        if ((k4.z >> 20) <= B) { unsigned s = atomicAdd(&g_cnt, 1u); if (s < CAND_CAP) g_cand[s] = (((unsigned long long)k4.z) << 32) | (base + 2); }
        if ((k4.w >> 20) <= B) { unsigned s = atomicAdd(&g_cnt, 1u); if (s < CAND_CAP) g_cand[s] = (((unsigned long long)k4.w) << 32) | (base + 3); }
    }
}

// ---------------- stage 3: parallel rank-by-counting (16 threads/slot) + decode ----------------
__global__ void __launch_bounds__(256) k_rank(const float4* __restrict__ anchors,
                                              const float4* __restrict__ reg) {
    __shared__ unsigned long long s[CAND_CAP];
    __shared__ unsigned sn;
    int t = threadIdx.x;
    if (t == 0) { unsigned c = g_cnt; sn = (c > CAND_CAP) ? CAND_CAP : c; }
    __syncthreads();
    unsigned n = sn;
    for (int i = t; i < (int)n; i += 256) s[i] = g_cand[i];
    __syncthreads();

    unsigned gt   = blockIdx.x * 256 + t;   // 0..32767
    unsigned slot = gt >> 4;                // 0..2047
    unsigned sub  = gt & 15;
    bool live = (slot < n);

    unsigned long long mine = live ? s[slot] : 0ull;
    unsigned r = 0;
    if (live) {
        unsigned chunk = (n + 15) >> 4;
        unsigned j0 = sub * chunk;
        unsigned j1 = j0 + chunk; if (j1 > n) j1 = n;
        for (unsigned j = j0; j < j1; j++) r += (s[j] < mine);
    }
    r += __shfl_xor_sync(0xFFFFFFFFu, r, 1);
    r += __shfl_xor_sync(0xFFFFFFFFu, r, 2);
    r += __shfl_xor_sync(0xFFFFFFFFu, r, 4);
    r += __shfl_xor_sync(0xFFFFFFFFu, r, 8);

    if (live && sub == 0 && r < NKEEP) {
        unsigned idx = (unsigned)mine;
        float m  = __uint_as_float((unsigned)(mine >> 32));
        float sc = 1.0f - m;

        float4 an = anchors[idx];
        float4 dg = reg[idx];
        float wa = an.z - an.x, ha = an.w - an.y;
        float cxa = an.x + 0.5f * wa, cya = an.y + 0.5f * ha;
        float cx = cxa + dg.x * wa, cy = cya + dg.y * ha;
        float w  = wa * expf(dg.z), hh = ha * expf(dg.w);
        float x1 = fminf(fmaxf(cx - 0.5f * w, 0.0f), 1535.0f);
        float y1 = fminf(fmaxf(cy - 0.5f * hh, 0.0f), 1535.0f);
        float x2 = fminf(fmaxf(cx + 0.5f * w, 0.0f), 1535.0f);
        float y2 = fminf(fmaxf(cy + 0.5f * hh, 0.0f), 1535.0f);

        g_box[r]    = make_float4(x1, y1, x2, y2);
        g_area[r]   = fmaxf(x2 - x1, 0.0f) * fmaxf(y2 - y1, 0.0f);
        g_cscore[r] = sc;
        g_ccls[r]   = g_argmax[idx];
    }
}

// ---------------- stage 4: suppression mask (smem-staged boxes) ----------------
__global__ void __launch_bounds__(256) k_iou() {
    __shared__ float4 sbox[NKEEP];
    __shared__ float  sarea[NKEEP];
    int t = threadIdx.x;
    for (int i = t; i < NKEEP; i += 256) { sbox[i] = g_box[i]; sarea[i] = g_area[i]; }
    __syncthreads();

    int W    = blockIdx.x * 8 + (t >> 5);   // 0..1023
    int lane = t & 31;
    int jw    = W & 31;
    int chunk = W >> 5;
    int i0   = chunk * 32;
    int iend = i0 + 32; if (iend > NKEEP) iend = NKEEP;
    int j = jw * 32 + lane;
    bool jv = (j < NKEEP);
    float jx1 = 0, jy1 = 0, jx2 = 0, jy2 = 0, ja = 0;
    if (jv) {
        float4 b = sbox[j];
        jx1 = b.x; jy1 = b.y; jx2 = b.z; jy2 = b.w;
        ja = sarea[j];
    }
    for (int i = i0; i < iend; i++) {
        float4 bi = sbox[i];
        float ai  = sarea[i];
        float iw = fminf(bi.z, jx2) - fmaxf(bi.x, jx1); iw = fmaxf(iw, 0.0f);
        float ih = fminf(bi.w, jy2) - fmaxf(bi.y, jy1); ih = fmaxf(ih, 0.0f);
        float inter = iw * ih;
        float uni   = ai + ja - inter;
        bool pred = jv && (inter / fmaxf(uni, 1e-8f) > 0.5f);
        unsigned m = __ballot_sync(0xFFFFFFFFu, pred);
        if (lane == 0) g_sup[i * 32 + jw] = m;
    }
}

// ---------------- stage 5: tile-blocked sequential NMS + output ----------------
__global__ void __launch_bounds__(256) k_scan(float* __restrict__ out) {
    extern __shared__ unsigned ssup[];   // 1024 rows x 33 words (padded, conflict-free)
    __shared__ unsigned svalid[32];
    __shared__ unsigned skeep[32];
    int tid = threadIdx.x;

    // stage sup matrix into padded layout (+ zero tail rows 1000..1023)
    for (int idx = tid; idx < 32768; idx += 256) {
        int r = idx >> 5, w = idx & 31;
        ssup[r * SCAN_STRIDE + w] = (r < NKEEP) ? g_sup[idx] : 0u;
    }
    for (int base = 0; base < 1024; base += 256) {
        int i = base + tid;
        float sc = (i < NKEEP) ? g_cscore[i] : 0.0f;
        unsigned bm = __ballot_sync(0xFFFFFFFFu, sc > 0.5f);
        if ((tid & 31) == 0) svalid[i >> 5] = bm;
    }
    __syncthreads();

    if (tid < 32) {
        int lane = tid;
        unsigned rem = 0;       // bit s = index 32*s + lane suppressed by earlier kept
        unsigned keepw = 0;     // keep word for tile == lane
        unsigned validw = svalid[lane];
        for (int t = 0; t < 32; t++) {
            unsigned rowv[32];
#pragma unroll
            for (int b = 0; b < 32; b++)
                rowv[b] = ssup[(32 * t + b) * SCAN_STRIDE + t];   // broadcast LDS
            unsigned W = __ballot_sync(0xFFFFFFFFu, (rem >> t) & 1u);
            unsigned V = __shfl_sync(0xFFFFFFFFu, validw, t);
            unsigned K = 0;
#pragma unroll
            for (int b = 0; b < 32; b++) {
                if (((V >> b) & 1u) && !((W >> b) & 1u) && ((rowv[b] & K) == 0u))
                    K |= 1u << b;
            }
            if (lane == t) keepw = K;
#pragma unroll
            for (int s = 1; s < 32; s++) {
                if (s > t) {
                    unsigned c = ssup[(32 * s + lane) * SCAN_STRIDE + t];  // conflict-free
                    if (c & K) rem |= 1u << s;
                }
            }
        }
        skeep[lane] = keepw;
    }
    __syncthreads();

    for (int base = 0; base < NKEEP; base += 256) {
        int i = base + tid;
        if (i < NKEEP) {
            bool kp = (skeep[i >> 5] >> (i & 31)) & 1u;
            out[i]         = kp ? g_cscore[i] : 0.0f;
            out[NKEEP + i] = kp ? (float)g_ccls[i] : -1.0f;
            float4 b = kp ? g_box[i] : make_float4(0, 0, 0, 0);
            ((float4*)(out + 2 * NKEEP))[i] = b;
        }
    }
}

// ---------------- launch ----------------
extern "C" void kernel_launch(void* const* d_in, const int* in_sizes, int n_in,
                              void* d_out, int out_size) {
    const float*  cla     = (const float*)d_in[0];
    const float4* reg     = (const float4*)d_in[1];
    const float4* anchors = (const float4*)d_in[2];
    int A = in_sizes[0] / 80;
    float* out = (float*)d_out;

    const int scan_smem = 1024 * SCAN_STRIDE * sizeof(unsigned);  // 135168 B
    cudaFuncSetAttribute(k_scan, cudaFuncAttributeMaxDynamicSharedMemorySize, scan_smem);

    k_init<<<1, 1024>>>();
    k_reduce<<<1184, 256>>>(cla, A);
    k_compact<<<592, 256>>>(A / 4);
    k_rank<<<128, 256>>>(anchors, reg);
    k_iou<<<128, 256>>>();
    k_scan<<<1, 256, scan_smem>>>(out);
}